// round 2
// baseline (speedup 1.0000x reference)
#include <cuda_runtime.h>
#include <math.h>
#include <stdint.h>

#define BB      4
#define SS      2048
#define DMODEL  1024
#define NH      16
#define HDIM    64
#define MR      (BB*SS)

// ---------------------------------------------------------------------------
// Scratch
// ---------------------------------------------------------------------------
__device__ float g_Qp[MR*DMODEL];
__device__ float g_Kp[MR*DMODEL];
__device__ float g_Vp[MR*DMODEL];
__device__ float g_Ao[MR*DMODEL];
__device__ float g_cm[BB*NH*SS];
__device__ float g_cr[BB*NH*SS];

// ---------------------------------------------------------------------------
// tf32 helpers
// ---------------------------------------------------------------------------
__device__ __forceinline__ float f2tf(float x){
    uint32_t u; asm("cvt.rna.tf32.f32 %0, %1;" : "=r"(u) : "f"(x));
    return __uint_as_float(u);
}

__device__ __forceinline__ void mma8(float* d,
    float a0, float a1, float a2, float a3, float b0, float b1)
{
    asm volatile(
        "mma.sync.aligned.m16n8k8.row.col.f32.tf32.tf32.f32 "
        "{%0,%1,%2,%3}, {%4,%5,%6,%7}, {%8,%9}, {%0,%1,%2,%3};\n"
        : "+f"(d[0]), "+f"(d[1]), "+f"(d[2]), "+f"(d[3])
        : "r"(__float_as_uint(a0)), "r"(__float_as_uint(a1)),
          "r"(__float_as_uint(a2)), "r"(__float_as_uint(a3)),
          "r"(__float_as_uint(b0)), "r"(__float_as_uint(b1)));
}

// Fragment-permuted smem layouts.
// A-frag (m16k8): elem (m,k) -> [(m>>4)*NDC + (k>>3)][lane=(m&7)*4+(k&3)][reg]
//   reg = ((k_in_chunk>=4)<<1) | (m_in_tile>=8)
__device__ __forceinline__ int a_off(int m, int k, int NDC){
    return (((m>>4)*NDC + (k>>3))*32 + (((m&7)<<2)|(k&3)))*4
           + ((((k>>2)&1)<<1) | ((m>>3)&1));
}
// B-frag (k8n8): elem (k,n) -> [(n>>3)*NKC + (k>>3)][lane=(n&7)*4+(k&3)][reg=k_in_chunk>=4]
__device__ __forceinline__ int b_off(int k, int n, int NKC){
    return (((n>>3)*NKC + (k>>3))*32 + (((n&7)<<2)|(k&3)))*2 + ((k>>2)&1);
}

// ---------------------------------------------------------------------------
// Kernel 1: C = A[M,K] @ W[K,N] + bias, split-tf32 (3 mma passes).
// Block 128x128, BK=8, 256 thr = 8 warps (2x4), warp tile 64x32.
// ---------------------------------------------------------------------------
__global__ __launch_bounds__(256,1) void proj3(
    const float* __restrict__ A, const float* __restrict__ W,
    const float* __restrict__ bias, float* __restrict__ C,
    int M, int N, int K)
{
    __shared__ float Ah[1024], Al[1024], Bh[1024], Bl[1024];
    const int tid = threadIdx.x, lane = tid & 31, w = tid >> 5;
    const int wy = w >> 2, wx = w & 3;
    const int brow = blockIdx.y << 7, bcol = blockIdx.x << 7;

    const int am = tid >> 1, ak = (tid & 1) << 2;
    const int wk = tid >> 5, wn = (tid & 31) << 2;

    float acc[4][4][4];
#pragma unroll
    for (int mt = 0; mt < 4; mt++)
#pragma unroll
        for (int nt = 0; nt < 4; nt++)
#pragma unroll
            for (int j = 0; j < 4; j++) acc[mt][nt][j] = 0.f;

    const float* Aptr = A + (size_t)(brow + am) * K + ak;
    const float* Wptr = W + (size_t)wk * N + bcol + wn;

    float4 av = *(const float4*)Aptr;
    float4 wv = *(const float4*)Wptr;

    for (int k0 = 0; k0 < K; k0 += 8) {
        {
            float vv[4] = {av.x, av.y, av.z, av.w};
#pragma unroll
            for (int j = 0; j < 4; j++) {
                float hi = f2tf(vv[j]), lo = f2tf(vv[j] - hi);
                int o = a_off(am, ak + j, 1);
                Ah[o] = hi; Al[o] = lo;
            }
            float ww[4] = {wv.x, wv.y, wv.z, wv.w};
#pragma unroll
            for (int j = 0; j < 4; j++) {
                float hi = f2tf(ww[j]), lo = f2tf(ww[j] - hi);
                int o = b_off(wk, wn + j, 1);
                Bh[o] = hi; Bl[o] = lo;
            }
        }
        __syncthreads();
        if (k0 + 8 < K) {
            av = *(const float4*)(Aptr + k0 + 8);
            wv = *(const float4*)(Wptr + (size_t)(k0 + 8) * N);
        }
        float4 ah[4], al[4]; float2 bhf[4], blf[4];
#pragma unroll
        for (int mt = 0; mt < 4; mt++) {
            int o = ((wy*4 + mt)*32 + lane)*4;
            ah[mt] = *(const float4*)&Ah[o];
            al[mt] = *(const float4*)&Al[o];
        }
#pragma unroll
        for (int nt = 0; nt < 4; nt++) {
            int o = ((wx*4 + nt)*32 + lane)*2;
            bhf[nt] = *(const float2*)&Bh[o];
            blf[nt] = *(const float2*)&Bl[o];
        }
#pragma unroll
        for (int mt = 0; mt < 4; mt++)
#pragma unroll
            for (int nt = 0; nt < 4; nt++) {
                mma8(acc[mt][nt], ah[mt].x, ah[mt].y, ah[mt].z, ah[mt].w, bhf[nt].x, bhf[nt].y);
                mma8(acc[mt][nt], al[mt].x, al[mt].y, al[mt].z, al[mt].w, bhf[nt].x, bhf[nt].y);
                mma8(acc[mt][nt], ah[mt].x, ah[mt].y, ah[mt].z, ah[mt].w, blf[nt].x, blf[nt].y);
            }
        __syncthreads();
    }

#pragma unroll
    for (int mt = 0; mt < 4; mt++)
#pragma unroll
        for (int nt = 0; nt < 4; nt++) {
            int row = brow + wy*64 + mt*16 + (lane >> 2);
            int col = bcol + wx*32 + nt*8 + ((lane & 3) << 1);
            float b0 = bias[col], b1 = bias[col+1];
            *(float2*)(C + (size_t)row*N + col) =
                make_float2(acc[mt][nt][0]+b0, acc[mt][nt][1]+b1);
            *(float2*)(C + (size_t)(row+8)*N + col) =
                make_float2(acc[mt][nt][2]+b0, acc[mt][nt][3]+b1);
        }
}

// ---------------------------------------------------------------------------
// Kernel 2: column softmax stats via split-tf32 mma.
// grid (BH=64, ktile=16); block 256 = 8 warps; warp covers 16 k-cols, all q.
// K fragments resident in registers; Q tiles streamed through perm smem.
// ---------------------------------------------------------------------------
__global__ __launch_bounds__(256,1) void col_stats3(
    const float* __restrict__ Qp, const float* __restrict__ Kp,
    float* __restrict__ cm, float* __restrict__ cr)
{
    extern __shared__ float sm[];
    float* SH = sm;            // 8192
    float* SL = sm + 8192;     // 8192
    const int tid = threadIdx.x, lane = tid & 31, w = tid >> 5;
    const int bh = blockIdx.x, kt0 = blockIdx.y << 7;
    const int b = bh >> 4, h = bh & 15;
    const size_t base = (size_t)b * SS * DMODEL + (size_t)h * HDIM;

    // stage K tile [128k x 64d] -> B-perm (NKC=8)
#pragma unroll
    for (int it = 0; it < 8; it++) {
        int idx4 = it*256 + tid;
        int kc = idx4 >> 4, d4 = (idx4 & 15) << 2;
        float4 v = *(const float4*)(Kp + base + (size_t)(kt0+kc)*DMODEL + d4);
        float vv[4] = {v.x, v.y, v.z, v.w};
#pragma unroll
        for (int j = 0; j < 4; j++) {
            float hi = f2tf(vv[j]), lo = f2tf(vv[j] - hi);
            int o = b_off(d4 + j, kc, 8);
            SH[o] = hi; SL[o] = lo;
        }
    }
    __syncthreads();
    float2 kbh[2][8], kbl[2][8];
#pragma unroll
    for (int nt2 = 0; nt2 < 2; nt2++)
#pragma unroll
        for (int dc = 0; dc < 8; dc++) {
            int o = (((w*2 + nt2)*8 + dc)*32 + lane)*2;
            kbh[nt2][dc] = *(const float2*)&SH[o];
            kbl[nt2][dc] = *(const float2*)&SL[o];
        }

    float mst[4] = {-1e30f, -1e30f, -1e30f, -1e30f};
    float zst[4] = {0.f, 0.f, 0.f, 0.f};

    for (int qt = 0; qt < 16; qt++) {
        __syncthreads();
        // stage Q tile [128q x 64d] -> A-perm (NDC=8)
#pragma unroll
        for (int it = 0; it < 8; it++) {
            int idx4 = it*256 + tid;
            int q = idx4 >> 4, d4 = (idx4 & 15) << 2;
            float4 v = *(const float4*)(Qp + base + (size_t)(qt*128 + q)*DMODEL + d4);
            float vv[4] = {v.x, v.y, v.z, v.w};
#pragma unroll
            for (int j = 0; j < 4; j++) {
                float hi = f2tf(vv[j]), lo = f2tf(vv[j] - hi);
                int o = a_off(q, d4 + j, 8);
                SH[o] = hi; SL[o] = lo;
            }
        }
        __syncthreads();

        float acc[8][2][4];
#pragma unroll
        for (int mt = 0; mt < 8; mt++)
#pragma unroll
            for (int nt2 = 0; nt2 < 2; nt2++)
#pragma unroll
                for (int j = 0; j < 4; j++) acc[mt][nt2][j] = 0.f;

#pragma unroll
        for (int mt = 0; mt < 8; mt++)
#pragma unroll
            for (int dc = 0; dc < 8; dc++) {
                int o = ((mt*8 + dc)*32 + lane)*4;
                float4 qh = *(const float4*)&SH[o];
                float4 ql = *(const float4*)&SL[o];
#pragma unroll
                for (int nt2 = 0; nt2 < 2; nt2++) {
                    mma8(acc[mt][nt2], qh.x,qh.y,qh.z,qh.w, kbh[nt2][dc].x, kbh[nt2][dc].y);
                    mma8(acc[mt][nt2], ql.x,ql.y,ql.z,ql.w, kbh[nt2][dc].x, kbh[nt2][dc].y);
                    mma8(acc[mt][nt2], qh.x,qh.y,qh.z,qh.w, kbl[nt2][dc].x, kbl[nt2][dc].y);
                }
            }

        // online column stats (cols = f(lane&3); allreduce over lane>>2 groups)
#pragma unroll
        for (int nt2 = 0; nt2 < 2; nt2++)
#pragma unroll
            for (int hh = 0; hh < 2; hh++) {
                int si = nt2*2 + hh;
                float tmax = -1e30f;
#pragma unroll
                for (int mt = 0; mt < 8; mt++)
                    tmax = fmaxf(tmax, fmaxf(acc[mt][nt2][hh], acc[mt][nt2][hh+2]));
                tmax = fmaxf(tmax, __shfl_xor_sync(0xffffffffu, tmax, 4));
                tmax = fmaxf(tmax, __shfl_xor_sync(0xffffffffu, tmax, 8));
                tmax = fmaxf(tmax, __shfl_xor_sync(0xffffffffu, tmax, 16));
                float mn = fmaxf(mst[si], tmax);
                float ts = 0.f;
#pragma unroll
                for (int mt = 0; mt < 8; mt++)
                    ts += __expf(acc[mt][nt2][hh] - mn) + __expf(acc[mt][nt2][hh+2] - mn);
                ts += __shfl_xor_sync(0xffffffffu, ts, 4);
                ts += __shfl_xor_sync(0xffffffffu, ts, 8);
                ts += __shfl_xor_sync(0xffffffffu, ts, 16);
                zst[si] = zst[si] * __expf(mst[si] - mn) + ts;
                mst[si] = mn;
            }
    }

    if (lane < 4) {
#pragma unroll
        for (int nt2 = 0; nt2 < 2; nt2++)
#pragma unroll
            for (int hh = 0; hh < 2; hh++) {
                int col = kt0 + w*16 + nt2*8 + lane*2 + hh;
                cm[(size_t)bh*SS + col] = mst[nt2*2 + hh];
                cr[(size_t)bh*SS + col] = 1.0f / (8.0f * zst[nt2*2 + hh]);
            }
    }
}

// ---------------------------------------------------------------------------
// Kernel 3: fused score recompute + exp-scale + E@V.
// grid (BH=64, qtile=16); block 256 = 8 warps; warp = 16 q-rows.
// smem: Q-perm hi/lo (64KB) resident; per k-iter K-perm hi/lo (64KB, reused
// for E-perm) and V-perm hi/lo (64KB); stats 1KB.
// ---------------------------------------------------------------------------
#define ATT_SMEM_F  (49408)
#define ATT_SMEM_B  (ATT_SMEM_F*4)

__global__ __launch_bounds__(256,1) void attn_av3(
    const float* __restrict__ Qp, const float* __restrict__ Kp,
    const float* __restrict__ Vp, const float* __restrict__ cm,
    const float* __restrict__ cr, float* __restrict__ Ao)
{
    extern __shared__ float sm[];
    float* QH = sm;              // 8192
    float* QL = sm + 8192;       // 8192
    float* R1 = sm + 16384;      // 16384: K hi @0, K lo @8192; later E (whole)
    float* VH = sm + 32768;      // 8192
    float* VL = sm + 40960;      // 8192
    float* mS = sm + 49152;      // 128
    float* rS = sm + 49280;      // 128

    const int tid = threadIdx.x, lane = tid & 31, w = tid >> 5;
    const int bh = blockIdx.x, qt0 = blockIdx.y << 7;
    const int b = bh >> 4, h = bh & 15;
    const size_t base = (size_t)b * SS * DMODEL + (size_t)h * HDIM;

    // stage Q tile [128q x 64d] -> A-perm hi/lo (NDC=8)
#pragma unroll
    for (int it = 0; it < 8; it++) {
        int idx4 = it*256 + tid;
        int q = idx4 >> 4, d4 = (idx4 & 15) << 2;
        float4 v = *(const float4*)(Qp + base + (size_t)(qt0 + q)*DMODEL + d4);
        float vv[4] = {v.x, v.y, v.z, v.w};
#pragma unroll
        for (int j = 0; j < 4; j++) {
            float hi = f2tf(vv[j]), lo = f2tf(vv[j] - hi);
            int o = a_off(q, d4 + j, 8);
            QH[o] = hi; QL[o] = lo;
        }
    }

    float accO[8][4];
#pragma unroll
    for (int nt = 0; nt < 8; nt++)
#pragma unroll
        for (int j = 0; j < 4; j++) accO[nt][j] = 0.f;

    for (int kt = 0; kt < 16; kt++) {
        __syncthreads();     // prev iter's EV-mma done; Q staging visible (iter 0)
        int k0 = kt << 7;
        // stage K -> R1 (B-perm NKC=8, hi/lo), V -> VH/VL (B-perm NKC=16)
#pragma unroll
        for (int it = 0; it < 8; it++) {
            int idx4 = it*256 + tid;
            int kr = idx4 >> 4, d4 = (idx4 & 15) << 2;
            float4 kv = *(const float4*)(Kp + base + (size_t)(k0 + kr)*DMODEL + d4);
            float4 vv = *(const float4*)(Vp + base + (size_t)(k0 + kr)*DMODEL + d4);
            float ka[4] = {kv.x, kv.y, kv.z, kv.w};
            float va[4] = {vv.x, vv.y, vv.z, vv.w};
#pragma unroll
            for (int j = 0; j < 4; j++) {
                float hi = f2tf(ka[j]), lo = f2tf(ka[j] - hi);
                int o = b_off(d4 + j, kr, 8);
                R1[o] = hi; R1[8192 + o] = lo;
                float vh = f2tf(va[j]), vlo = f2tf(va[j] - vh);
                int o2 = b_off(kr, d4 + j, 16);
                VH[o2] = vh; VL[o2] = vlo;
            }
        }
        if (tid < 128) {
            mS[tid] = cm[(size_t)bh*SS + k0 + tid];
            rS[tid] = cr[(size_t)bh*SS + k0 + tid];
        }
        __syncthreads();

        // S = Q K^T  (warp's 16 q-rows x 128 k-cols), split-tf32
        float accs[16][4];
#pragma unroll
        for (int nt = 0; nt < 16; nt++)
#pragma unroll
            for (int j = 0; j < 4; j++) accs[nt][j] = 0.f;

#pragma unroll
        for (int dc = 0; dc < 8; dc++) {
            int oq = ((w*8 + dc)*32 + lane)*4;
            float4 qh = *(const float4*)&QH[oq];
            float4 ql = *(const float4*)&QL[oq];
#pragma unroll
            for (int nt = 0; nt < 16; nt++) {
                int ob = ((nt*8 + dc)*32 + lane)*2;
                float2 bh2 = *(const float2*)&R1[ob];
                float2 bl2 = *(const float2*)&R1[8192 + ob];
                mma8(accs[nt], qh.x,qh.y,qh.z,qh.w, bh2.x, bh2.y);
                mma8(accs[nt], ql.x,ql.y,ql.z,ql.w, bh2.x, bh2.y);
                mma8(accs[nt], qh.x,qh.y,qh.z,qh.w, bl2.x, bl2.y);
            }
        }
        __syncthreads();     // all warps finished reading K from R1

        // E = exp(s - m[k]) * r[k], written to R1 as A-perm (NDC=16)
#pragma unroll
        for (int nt = 0; nt < 16; nt++)
#pragma unroll
            for (int j = 0; j < 4; j++) {
                int kloc = (nt << 3) + ((lane & 3) << 1) + (j & 1);
                float e = __expf(accs[nt][j] - mS[kloc]) * rS[kloc];
                int rr = (lane >> 2) + ((j >> 1) << 3);
                int ki = kloc & 7;
                int o = ((w*16 + nt)*32 + ((rr & 7) << 2) + (ki & 3))*4
                        + (((ki >> 2) & 1) << 1) + ((rr >> 3) & 1);
                R1[o] = f2tf(e);
            }
        __syncthreads();

        // O += E @ V   (E single tf32, V split)
#pragma unroll
        for (int kc = 0; kc < 16; kc++) {
            int oa = ((w*16 + kc)*32 + lane)*4;
            float4 ea = *(const float4*)&R1[oa];
#pragma unroll
            for (int nt = 0; nt < 8; nt++) {
                int ob = ((nt*16 + kc)*32 + lane)*2;
                float2 vh = *(const float2*)&VH[ob];
                float2 vl = *(const float2*)&VL[ob];
                mma8(accO[nt], ea.x, ea.y, ea.z, ea.w, vh.x, vh.y);
                mma8(accO[nt], ea.x, ea.y, ea.z, ea.w, vl.x, vl.y);
            }
        }
    }

    // write O tile, merged-head layout [b, q, h*64+d]
#pragma unroll
    for (int nt = 0; nt < 8; nt++) {
        int row = qt0 + w*16 + (lane >> 2);
        int col = (nt << 3) + ((lane & 3) << 1);
        *(float2*)(Ao + base + (size_t)row*DMODEL + col) =
            make_float2(accO[nt][0], accO[nt][1]);
        *(float2*)(Ao + base + (size_t)(row+8)*DMODEL + col) =
            make_float2(accO[nt][2], accO[nt][3]);
    }
}

// ---------------------------------------------------------------------------
// Launch
// ---------------------------------------------------------------------------
extern "C" void kernel_launch(void* const* d_in, const int* in_sizes, int n_in,
                              void* d_out, int out_size)
{
    const float* qin = (const float*)d_in[0];
    const float* kin = (const float*)d_in[1];
    const float* vin = (const float*)d_in[2];
    const float* Wq  = (const float*)d_in[3];
    const float* bq  = (const float*)d_in[4];
    const float* Wk  = (const float*)d_in[5];
    const float* bk  = (const float*)d_in[6];
    const float* Wv  = (const float*)d_in[7];
    const float* bv  = (const float*)d_in[8];
    const float* Wo  = (const float*)d_in[9];
    const float* bo  = (const float*)d_in[10];

    float *Qp, *Kp, *Vp, *Ao, *cm, *cr;
    cudaGetSymbolAddress((void**)&Qp, g_Qp);
    cudaGetSymbolAddress((void**)&Kp, g_Kp);
    cudaGetSymbolAddress((void**)&Vp, g_Vp);
    cudaGetSymbolAddress((void**)&Ao, g_Ao);
    cudaGetSymbolAddress((void**)&cm, g_cm);
    cudaGetSymbolAddress((void**)&cr, g_cr);

    cudaFuncSetAttribute(col_stats3, cudaFuncAttributeMaxDynamicSharedMemorySize,
                         65536);
    cudaFuncSetAttribute(attn_av3, cudaFuncAttributeMaxDynamicSharedMemorySize,
                         ATT_SMEM_B);

    dim3 gGemm(DMODEL/128, MR/128);   // (8, 64)

    proj3<<<gGemm, 256>>>(qin, Wq, bq, Qp, MR, DMODEL, DMODEL);
    proj3<<<gGemm, 256>>>(kin, Wk, bk, Kp, MR, DMODEL, DMODEL);
    proj3<<<gGemm, 256>>>(vin, Wv, bv, Vp, MR, DMODEL, DMODEL);

    col_stats3<<<dim3(BB*NH, SS/128), 256, 65536>>>(Qp, Kp, cm, cr);

    attn_av3<<<dim3(BB*NH, SS/128), 256, ATT_SMEM_B>>>(Qp, Kp, Vp, cm, cr, Ao);

    proj3<<<gGemm, 256>>>(Ao, Wo, bo, (float*)d_out, MR, DMODEL, DMODEL);
}

// round 3
// speedup vs baseline: 2.2624x; 2.2624x over previous
#include <cuda_runtime.h>
#include <cuda_bf16.h>
#include <math.h>
#include <stdint.h>

#define BB      4
#define SS      2048
#define DMODEL  1024
#define NH      16
#define HDIM    64
#define MR      (BB*SS)

// ---------------------------------------------------------------------------
// Scratch
// ---------------------------------------------------------------------------
__device__ float g_Qp[MR*DMODEL];
__device__ float g_Kp[MR*DMODEL];
__device__ float g_Vp[MR*DMODEL];
__device__ float g_Ao[MR*DMODEL];
__device__ float g_cm[BB*NH*SS];
__device__ float g_cr[BB*NH*SS];

// ---------------------------------------------------------------------------
// bf16 split helpers: x = hi + lo with ~16-bit effective mantissa
// ---------------------------------------------------------------------------
__device__ __forceinline__ void split2(float x, float y, uint32_t& hi, uint32_t& lo){
    __nv_bfloat16 hx = __float2bfloat16(x);
    __nv_bfloat16 hy = __float2bfloat16(y);
    float rx = x - __bfloat162float(hx);
    float ry = y - __bfloat162float(hy);
    __nv_bfloat162 h2 = __halves2bfloat162(hx, hy);
    __nv_bfloat162 l2 = __halves2bfloat162(__float2bfloat16(rx), __float2bfloat16(ry));
    hi = *reinterpret_cast<uint32_t*>(&h2);
    lo = *reinterpret_cast<uint32_t*>(&l2);
}

// mma.m16n8k16 bf16: D += A*B (fp32 accum)
__device__ __forceinline__ void mma16(float* d,
    uint32_t a0, uint32_t a1, uint32_t a2, uint32_t a3,
    uint32_t b0, uint32_t b1)
{
    asm volatile(
        "mma.sync.aligned.m16n8k16.row.col.f32.bf16.bf16.f32 "
        "{%0,%1,%2,%3}, {%4,%5,%6,%7}, {%8,%9}, {%0,%1,%2,%3};\n"
        : "+f"(d[0]), "+f"(d[1]), "+f"(d[2]), "+f"(d[3])
        : "r"(a0), "r"(a1), "r"(a2), "r"(a3), "r"(b0), "r"(b1));
}

// ---------------------------------------------------------------------------
// Kernel 1: C = A[M,K] @ W[K,N] + bias, 3-pass split-bf16.
// Block 128x128, BK=16, 256 thr = 8 warps (2x4), warp tile 64x32.
// Fragment-permuted smem (u32 = bf16 pair along k).
// A-perm off: ((mt*NKC+kc)*32 + (m&7)*4 + ((k&7)>>1))*4 + ((k>>3)&1)*2 + ((m>>3)&1)
// B-perm off: ((nt*NKC+kc)*32 + (n&7)*4 + ((k&7)>>1))*2 + ((k>>3)&1)
// ---------------------------------------------------------------------------
__global__ __launch_bounds__(256) void proj_bf(
    const float* __restrict__ A, const float* __restrict__ W,
    const float* __restrict__ bias, float* __restrict__ C,
    int M, int N, int K)
{
    __shared__ uint32_t AhU[1024], AlU[1024], BhU[1024], BlU[1024];
    const int tid = threadIdx.x, lane = tid & 31, w = tid >> 5;
    const int wy = w >> 2, wx = w & 3;
    const int brow = blockIdx.y << 7, bcol = blockIdx.x << 7;

    float acc[4][4][4];
#pragma unroll
    for (int mt = 0; mt < 4; mt++)
#pragma unroll
        for (int nt = 0; nt < 4; nt++)
#pragma unroll
            for (int j = 0; j < 4; j++) acc[mt][nt][j] = 0.f;

    const int am = tid >> 2, ak = (tid & 3) << 2;
    const float* ApA = A + (size_t)(brow + am) * K + ak;
    const float* ApB = ApA + (size_t)64 * K;
    const int wk = (tid >> 5) << 1, wn = (tid & 31) << 2;
    const float* Wp = W + (size_t)wk * N + bcol + wn;

    float4 avA = *(const float4*)ApA;
    float4 avB = *(const float4*)ApB;
    float4 wv0 = *(const float4*)Wp;
    float4 wv1 = *(const float4*)(Wp + N);

    // staging offsets (k-invariant parts)
    const int aoff = ((am >> 4) * 32 + ((am & 7) << 2) + ((ak & 7) >> 1)) * 4
                     + (((ak >> 3) & 1) << 1) + ((am >> 3) & 1);

    for (int k0 = 0; k0 < K; k0 += 16) {
        {
            uint32_t h, l;
            split2(avA.x, avA.y, h, l); AhU[aoff]       = h; AlU[aoff]       = l;
            split2(avA.z, avA.w, h, l); AhU[aoff+4]     = h; AlU[aoff+4]     = l;
            split2(avB.x, avB.y, h, l); AhU[aoff+512]   = h; AlU[aoff+512]   = l;
            split2(avB.z, avB.w, h, l); AhU[aoff+516]   = h; AlU[aoff+516]   = l;
            float w0a[4] = {wv0.x, wv0.y, wv0.z, wv0.w};
            float w1a[4] = {wv1.x, wv1.y, wv1.z, wv1.w};
#pragma unroll
            for (int j = 0; j < 4; j++) {
                int nn = wn + j;
                int offb = ((nn >> 3) * 32 + ((nn & 7) << 2) + ((wk & 7) >> 1)) * 2
                           + ((wk >> 3) & 1);
                split2(w0a[j], w1a[j], h, l); BhU[offb] = h; BlU[offb] = l;
            }
        }
        __syncthreads();
        if (k0 + 16 < K) {
            avA = *(const float4*)(ApA + k0 + 16);
            avB = *(const float4*)(ApB + k0 + 16);
            wv0 = *(const float4*)(Wp + (size_t)(k0 + 16) * N);
            wv1 = *(const float4*)(Wp + (size_t)(k0 + 17) * N);
        }
        uint4 ah[4], al[4]; uint2 bh[4], bl[4];
#pragma unroll
        for (int mt = 0; mt < 4; mt++) {
            int o = ((wy*4 + mt)*32 + lane)*4;
            ah[mt] = *(const uint4*)&AhU[o];
            al[mt] = *(const uint4*)&AlU[o];
        }
#pragma unroll
        for (int nt = 0; nt < 4; nt++) {
            int o = ((wx*4 + nt)*32 + lane)*2;
            bh[nt] = *(const uint2*)&BhU[o];
            bl[nt] = *(const uint2*)&BlU[o];
        }
#pragma unroll
        for (int mt = 0; mt < 4; mt++)
#pragma unroll
            for (int nt = 0; nt < 4; nt++) {
                mma16(acc[mt][nt], ah[mt].x, ah[mt].y, ah[mt].z, ah[mt].w, bh[nt].x, bh[nt].y);
                mma16(acc[mt][nt], al[mt].x, al[mt].y, al[mt].z, al[mt].w, bh[nt].x, bh[nt].y);
                mma16(acc[mt][nt], ah[mt].x, ah[mt].y, ah[mt].z, ah[mt].w, bl[nt].x, bl[nt].y);
            }
        __syncthreads();
    }

#pragma unroll
    for (int mt = 0; mt < 4; mt++)
#pragma unroll
        for (int nt = 0; nt < 4; nt++) {
            int row = brow + wy*64 + mt*16 + (lane >> 2);
            int col = bcol + wx*32 + nt*8 + ((lane & 3) << 1);
            float b0 = bias[col], b1 = bias[col+1];
            *(float2*)(C + (size_t)row*N + col) =
                make_float2(acc[mt][nt][0]+b0, acc[mt][nt][1]+b1);
            *(float2*)(C + (size_t)(row+8)*N + col) =
                make_float2(acc[mt][nt][2]+b0, acc[mt][nt][3]+b1);
        }
}

// ---------------------------------------------------------------------------
// Kernel 2: column softmax stats (max over q, sumexp over q) per key column.
// grid (BH=64, 16 key-tiles of 128); block 256 = 8 warps; warp owns 16 keys.
// K fragments resident in regs; Q tiles streamed through perm smem.
// ---------------------------------------------------------------------------
__global__ __launch_bounds__(256) void colstats_bf(
    const float* __restrict__ Qp, const float* __restrict__ Kp,
    float* __restrict__ cm, float* __restrict__ cr)
{
    __shared__ uint32_t SH[4096], SL[4096];
    const int tid = threadIdx.x, lane = tid & 31, w = tid >> 5;
    const int bh = blockIdx.x, kt0 = blockIdx.y << 7;
    const int b = bh >> 4, h = bh & 15;
    const size_t base = (size_t)b * SS * DMODEL + (size_t)h * HDIM;

    // stage K tile [128key x 64d] -> B-perm (NKC=4)
#pragma unroll
    for (int it = 0; it < 8; it++) {
        int u = it*256 + tid;
        int key = u >> 4, d = (u & 15) << 2;
        float4 v = *(const float4*)(Kp + base + (size_t)(kt0+key)*DMODEL + d);
        int off = (((key>>3)*4 + (d>>4))*32 + ((key&7)<<2) + ((d&7)>>1))*2 + ((d>>3)&1);
        uint32_t hh, ll;
        split2(v.x, v.y, hh, ll); SH[off]   = hh; SL[off]   = ll;
        split2(v.z, v.w, hh, ll); SH[off+2] = hh; SL[off+2] = ll;
    }
    __syncthreads();
    uint2 kbh[2][4], kbl[2][4];
#pragma unroll
    for (int nt2 = 0; nt2 < 2; nt2++)
#pragma unroll
        for (int kc = 0; kc < 4; kc++) {
            int o = (((w*2 + nt2)*4 + kc)*32 + lane)*2;
            kbh[nt2][kc] = *(const uint2*)&SH[o];
            kbl[nt2][kc] = *(const uint2*)&SL[o];
        }
    __syncthreads();   // done reading K; smem reused for Q

    float mst[4] = {-1e30f, -1e30f, -1e30f, -1e30f};
    float zst[4] = {0.f, 0.f, 0.f, 0.f};

    for (int qt = 0; qt < 16; qt++) {
        // stage Q tile [128q x 64d] -> A-perm (NKC=4)
#pragma unroll
        for (int it = 0; it < 8; it++) {
            int u = it*256 + tid;
            int q = u >> 4, d = (u & 15) << 2;
            float4 v = *(const float4*)(Qp + base + (size_t)(qt*128 + q)*DMODEL + d);
            int off = (((q>>4)*4 + (d>>4))*32 + ((q&7)<<2) + ((d&7)>>1))*4
                      + (((d>>3)&1)<<1) + ((q>>3)&1);
            uint32_t hh, ll;
            split2(v.x, v.y, hh, ll); SH[off]   = hh; SL[off]   = ll;
            split2(v.z, v.w, hh, ll); SH[off+4] = hh; SL[off+4] = ll;
        }
        __syncthreads();

        float acc[8][2][4];
#pragma unroll
        for (int mt = 0; mt < 8; mt++)
#pragma unroll
            for (int nt2 = 0; nt2 < 2; nt2++)
#pragma unroll
                for (int j = 0; j < 4; j++) acc[mt][nt2][j] = 0.f;

#pragma unroll
        for (int mt = 0; mt < 8; mt++)
#pragma unroll
            for (int kc = 0; kc < 4; kc++) {
                int o = ((mt*4 + kc)*32 + lane)*4;
                uint4 qh = *(const uint4*)&SH[o];
                uint4 ql = *(const uint4*)&SL[o];
#pragma unroll
                for (int nt2 = 0; nt2 < 2; nt2++) {
                    mma16(acc[mt][nt2], qh.x,qh.y,qh.z,qh.w, kbh[nt2][kc].x, kbh[nt2][kc].y);
                    mma16(acc[mt][nt2], ql.x,ql.y,ql.z,ql.w, kbh[nt2][kc].x, kbh[nt2][kc].y);
                    mma16(acc[mt][nt2], qh.x,qh.y,qh.z,qh.w, kbl[nt2][kc].x, kbl[nt2][kc].y);
                }
            }

        // online column stats; thread cols = 2*(lane&3)+{0,1}; reduce over g
#pragma unroll
        for (int nt2 = 0; nt2 < 2; nt2++)
#pragma unroll
            for (int hh = 0; hh < 2; hh++) {
                int si = nt2*2 + hh;
                float tmax = -1e30f;
#pragma unroll
                for (int mt = 0; mt < 8; mt++)
                    tmax = fmaxf(tmax, fmaxf(acc[mt][nt2][hh], acc[mt][nt2][hh+2]));
                tmax = fmaxf(tmax, __shfl_xor_sync(0xffffffffu, tmax, 4));
                tmax = fmaxf(tmax, __shfl_xor_sync(0xffffffffu, tmax, 8));
                tmax = fmaxf(tmax, __shfl_xor_sync(0xffffffffu, tmax, 16));
                float mn = fmaxf(mst[si], tmax);
                float ts = 0.f;
#pragma unroll
                for (int mt = 0; mt < 8; mt++)
                    ts += __expf(acc[mt][nt2][hh] - mn) + __expf(acc[mt][nt2][hh+2] - mn);
                ts += __shfl_xor_sync(0xffffffffu, ts, 4);
                ts += __shfl_xor_sync(0xffffffffu, ts, 8);
                ts += __shfl_xor_sync(0xffffffffu, ts, 16);
                zst[si] = zst[si] * __expf(mst[si] - mn) + ts;
                mst[si] = mn;
            }
        __syncthreads();   // before next Q staging overwrites SH/SL
    }

    if (lane < 4) {
#pragma unroll
        for (int nt2 = 0; nt2 < 2; nt2++)
#pragma unroll
            for (int hh = 0; hh < 2; hh++) {
                int col = kt0 + w*16 + nt2*8 + lane*2 + hh;
                cm[(size_t)bh*SS + col] = mst[nt2*2 + hh];
                cr[(size_t)bh*SS + col] = 1.0f / (8.0f * zst[nt2*2 + hh]);
            }
    }
}

// ---------------------------------------------------------------------------
// Kernel 3: fused score recompute + exp-scale + E@V. E stays in registers
// (C-frag lane map == A-frag lane map). k-tile 64. 2 syncs/iter.
// grid (BH=64, 16 q-tiles); block 256 = 8 warps; warp owns 16 q rows.
// ---------------------------------------------------------------------------
#define ATT_U32   (16384 + 128)
#define ATT_BYTES (ATT_U32*4)

__global__ __launch_bounds__(256) void attn_bf(
    const float* __restrict__ Qp, const float* __restrict__ Kp,
    const float* __restrict__ Vp, const float* __restrict__ cm,
    const float* __restrict__ cr, float* __restrict__ Ao)
{
    extern __shared__ uint32_t su[];
    uint32_t* QhU = su;               // 4096
    uint32_t* QlU = su + 4096;        // 4096
    uint32_t* KhU = su + 8192;        // 2048
    uint32_t* KlU = su + 10240;       // 2048
    uint32_t* VhU = su + 12288;       // 2048
    uint32_t* VlU = su + 14336;       // 2048
    float*    mS  = (float*)(su + 16384);   // 64
    float*    rS  = (float*)(su + 16448);   // 64

    const int tid = threadIdx.x, lane = tid & 31, w = tid >> 5;
    const int g = lane >> 2, t = lane & 3;
    const int bh = blockIdx.x, qt0 = blockIdx.y << 7;
    const int b = bh >> 4, h = bh & 15;
    const size_t base = (size_t)b * SS * DMODEL + (size_t)h * HDIM;

    // stage Q tile [128q x 64d] -> A-perm (resident)
#pragma unroll
    for (int it = 0; it < 8; it++) {
        int u = it*256 + tid;
        int q = u >> 4, d = (u & 15) << 2;
        float4 v = *(const float4*)(Qp + base + (size_t)(qt0 + q)*DMODEL + d);
        int off = (((q>>4)*4 + (d>>4))*32 + ((q&7)<<2) + ((d&7)>>1))*4
                  + (((d>>3)&1)<<1) + ((q>>3)&1);
        uint32_t hh, ll;
        split2(v.x, v.y, hh, ll); QhU[off]   = hh; QlU[off]   = ll;
        split2(v.z, v.w, hh, ll); QhU[off+4] = hh; QlU[off+4] = ll;
    }

    float accO[8][4];
#pragma unroll
    for (int nt = 0; nt < 8; nt++)
#pragma unroll
        for (int j = 0; j < 4; j++) accO[nt][j] = 0.f;

    for (int kt = 0; kt < 32; kt++) {
        const int k0 = kt << 6;
        __syncthreads();   // prev iter's mma reads done (iter0: Q staging done)

        // stage K [64key x 64d] -> B-perm (k-dim = d)
#pragma unroll
        for (int it = 0; it < 4; it++) {
            int u = it*256 + tid;
            int key = u >> 4, d = (u & 15) << 2;
            float4 kv = *(const float4*)(Kp + base + (size_t)(k0 + key)*DMODEL + d);
            int off = (((key>>3)*4 + (d>>4))*32 + ((key&7)<<2) + ((d&7)>>1))*2 + ((d>>3)&1);
            uint32_t hh, ll;
            split2(kv.x, kv.y, hh, ll); KhU[off]   = hh; KlU[off]   = ll;
            split2(kv.z, kv.w, hh, ll); KhU[off+2] = hh; KlU[off+2] = ll;
        }
        // stage V [64key x 64d] -> B-perm (k-dim = key, n-dim = d)
#pragma unroll
        for (int it = 0; it < 2; it++) {
            int u = it*256 + tid;
            int key = (u >> 4) << 1, d = (u & 15) << 2;
            float4 v0 = *(const float4*)(Vp + base + (size_t)(k0 + key)*DMODEL + d);
            float4 v1 = *(const float4*)(Vp + base + (size_t)(k0 + key + 1)*DMODEL + d);
            float a0[4] = {v0.x, v0.y, v0.z, v0.w};
            float a1[4] = {v1.x, v1.y, v1.z, v1.w};
#pragma unroll
            for (int j = 0; j < 4; j++) {
                int dd = d + j;
                int off = (((dd>>3)*4 + (key>>4))*32 + ((dd&7)<<2) + ((key&7)>>1))*2
                          + ((key>>3)&1);
                uint32_t hh, ll;
                split2(a0[j], a1[j], hh, ll); VhU[off] = hh; VlU[off] = ll;
            }
        }
        if (tid < 64) {
            mS[tid] = cm[(size_t)bh*SS + k0 + tid];
            rS[tid] = cr[(size_t)bh*SS + k0 + tid];
        }
        __syncthreads();

        // S = Q K^T for warp's 16 q rows x 64 keys
        float accs[8][4];
#pragma unroll
        for (int nt = 0; nt < 8; nt++)
#pragma unroll
            for (int j = 0; j < 4; j++) accs[nt][j] = 0.f;

#pragma unroll
        for (int kc = 0; kc < 4; kc++) {
            int oq = ((w*4 + kc)*32 + lane)*4;
            uint4 qh = *(const uint4*)&QhU[oq];
            uint4 ql = *(const uint4*)&QlU[oq];
#pragma unroll
            for (int nt = 0; nt < 8; nt++) {
                int ob = ((nt*4 + kc)*32 + lane)*2;
                uint2 kb = *(const uint2*)&KhU[ob];
                uint2 kl = *(const uint2*)&KlU[ob];
                mma16(accs[nt], qh.x,qh.y,qh.z,qh.w, kb.x, kb.y);
                mma16(accs[nt], ql.x,ql.y,ql.z,ql.w, kb.x, kb.y);
                mma16(accs[nt], qh.x,qh.y,qh.z,qh.w, kl.x, kl.y);
            }
        }

        // E = exp(s - m[k]) * r[k]; pure in-register repack C-frag -> A-frag
        uint32_t EH[4][4], EL[4][4];
#pragma unroll
        for (int nt = 0; nt < 8; nt++) {
            int kcp = nt >> 1, rb = (nt & 1) << 1;
            int c0 = nt*8 + t*2, c1 = c0 + 1;
            float m0 = mS[c0], m1 = mS[c1], r0 = rS[c0], r1 = rS[c1];
            float e00 = __expf(accs[nt][0] - m0) * r0;
            float e01 = __expf(accs[nt][1] - m1) * r1;
            float e10 = __expf(accs[nt][2] - m0) * r0;
            float e11 = __expf(accs[nt][3] - m1) * r1;
            uint32_t hh, ll;
            split2(e00, e01, hh, ll); EH[kcp][rb]   = hh; EL[kcp][rb]   = ll;
            split2(e10, e11, hh, ll); EH[kcp][rb+1] = hh; EL[kcp][rb+1] = ll;
        }

        // O += E @ V
#pragma unroll
        for (int kc = 0; kc < 4; kc++) {
#pragma unroll
            for (int nt = 0; nt < 8; nt++) {
                int ob = ((nt*4 + kc)*32 + lane)*2;
                uint2 vh = *(const uint2*)&VhU[ob];
                uint2 vl = *(const uint2*)&VlU[ob];
                mma16(accO[nt], EH[kc][0], EH[kc][1], EH[kc][2], EH[kc][3], vh.x, vh.y);
                mma16(accO[nt], EL[kc][0], EL[kc][1], EL[kc][2], EL[kc][3], vh.x, vh.y);
                mma16(accO[nt], EH[kc][0], EH[kc][1], EH[kc][2], EH[kc][3], vl.x, vl.y);
            }
        }
    }

    // write O tile, merged-head layout [b, q, h*64+d]
    const int row = qt0 + w*16 + g;
#pragma unroll
    for (int nt = 0; nt < 8; nt++) {
        int col = nt*8 + t*2;
        *(float2*)(Ao + base + (size_t)row*DMODEL + col) =
            make_float2(accO[nt][0], accO[nt][1]);
        *(float2*)(Ao + base + (size_t)(row+8)*DMODEL + col) =
            make_float2(accO[nt][2], accO[nt][3]);
    }
}

// ---------------------------------------------------------------------------
// Launch
// ---------------------------------------------------------------------------
extern "C" void kernel_launch(void* const* d_in, const int* in_sizes, int n_in,
                              void* d_out, int out_size)
{
    const float* qin = (const float*)d_in[0];
    const float* kin = (const float*)d_in[1];
    const float* vin = (const float*)d_in[2];
    const float* Wq  = (const float*)d_in[3];
    const float* bq  = (const float*)d_in[4];
    const float* Wk  = (const float*)d_in[5];
    const float* bk  = (const float*)d_in[6];
    const float* Wv  = (const float*)d_in[7];
    const float* bv  = (const float*)d_in[8];
    const float* Wo  = (const float*)d_in[9];
    const float* bo  = (const float*)d_in[10];

    float *Qp, *Kp, *Vp, *Ao, *cm, *cr;
    cudaGetSymbolAddress((void**)&Qp, g_Qp);
    cudaGetSymbolAddress((void**)&Kp, g_Kp);
    cudaGetSymbolAddress((void**)&Vp, g_Vp);
    cudaGetSymbolAddress((void**)&Ao, g_Ao);
    cudaGetSymbolAddress((void**)&cm, g_cm);
    cudaGetSymbolAddress((void**)&cr, g_cr);

    cudaFuncSetAttribute(attn_bf, cudaFuncAttributeMaxDynamicSharedMemorySize,
                         ATT_BYTES);

    dim3 gGemm(DMODEL/128, MR/128);   // (8, 64)

    proj_bf<<<gGemm, 256>>>(qin, Wq, bq, Qp, MR, DMODEL, DMODEL);
    proj_bf<<<gGemm, 256>>>(kin, Wk, bk, Kp, MR, DMODEL, DMODEL);
    proj_bf<<<gGemm, 256>>>(vin, Wv, bv, Vp, MR, DMODEL, DMODEL);

    colstats_bf<<<dim3(BB*NH, SS/128), 256>>>(Qp, Kp, cm, cr);

    attn_bf<<<dim3(BB*NH, SS/128), 256, ATT_BYTES>>>(Qp, Kp, Vp, cm, cr, Ao);

    proj_bf<<<gGemm, 256>>>(Ao, Wo, bo, (float*)d_out, MR, DMODEL, DMODEL);
}